// round 9
// baseline (speedup 1.0000x reference)
#include <cuda_runtime.h>
#include <cuda_bf16.h>
#include <cstdint>
#include <stdint.h>
#include <math.h>

#define BATCH   32
#define NCAPS   1152
#define ILEN    32
#define OCAPS   64
#define OLEN    32
#define CLU     4                  // CTAs per cluster (one cluster per batch)
#define NPC     (NCAPS / CLU)      // 288 input caps per CTA
#define OPC     (OCAPS / CLU)      // 16 output caps per CTA
#define TPB     1024
#define NWARP   32

// SMEM layout (float offsets)
#define XS_OFF  0                           // xs [288][32]        9216
#define PS_OFF  (XS_OFF + NPC * ILEN)       // ps [288][64]       18432
#define LP_OFF  (PS_OFF + NPC * OCAPS)      // lp [4][64][32]      8192
#define TS_OFF  (LP_OFF + 4 * OCAPS * 32)   // tS [64][36]         2304
#define SP_OFF  (TS_OFF + OCAPS * 36)       // sp [4][16][32]      2048
#define EX_OFF  (SP_OFF + CLU * OPC * 32)   // ex [2][16][9] f4    1152
#define SX_OFF  (EX_OFF + 2 * 16 * 9 * 4)   // sx [4][32]           128
#define SM_FLOATS (SX_OFF + CLU * 32)
#define SM_BYTES  (SM_FLOATS * 4)           // 165,888 B

__device__ __forceinline__ unsigned int smem_u32(const void* p) {
    unsigned int a;
    asm("{ .reg .u64 t; cvta.to.shared.u64 t, %1; cvt.u32.u64 %0, t; }"
        : "=r"(a) : "l"(p));
    return a;
}
__device__ __forceinline__ unsigned int mapa_rank(unsigned int laddr,
                                                  unsigned int rank) {
    unsigned int r;
    asm("mapa.shared::cluster.u32 %0, %1, %2;" : "=r"(r) : "r"(laddr), "r"(rank));
    return r;
}
__device__ __forceinline__ void st_clu(unsigned int raddr, float v) {
    asm volatile("st.shared::cluster.f32 [%0], %1;" :: "r"(raddr), "f"(v) : "memory");
}
#define CLUSTER_SYNC() do { \
    asm volatile("barrier.cluster.arrive.aligned;" ::: "memory"); \
    asm volatile("barrier.cluster.wait.aligned;" ::: "memory"); \
} while (0)

// packed fp32x2 helpers
__device__ __forceinline__ void ffma2(unsigned long long& d,
                                      unsigned long long a,
                                      unsigned long long b) {
    asm("fma.rn.f32x2 %0, %1, %2, %0;" : "+l"(d) : "l"(a), "l"(b));
}
__device__ __forceinline__ float2 unpack2(unsigned long long v) {
    float2 r;
    asm("mov.b64 {%0, %1}, %2;" : "=f"(r.x), "=f"(r.y) : "l"(v));
    return r;
}
__device__ __forceinline__ unsigned long long splat2(float v) {
    unsigned long long r;
    asm("mov.b64 %0, {%1, %1};" : "=l"(r) : "f"(v));
    return r;
}

// ---------------------------------------------------------------------------
// Persistent clustered kernel, 1024 threads (32 warps) per CTA.
// ---------------------------------------------------------------------------
__global__ void __cluster_dims__(CLU, 1, 1) __launch_bounds__(TPB, 1)
k_caps(const float* __restrict__ x, const float* __restrict__ w,
       float* __restrict__ out) {
    extern __shared__ float sm[];
    float* xs = sm + XS_OFF;
    float* ps = sm + PS_OFF;
    float* lp = sm + LP_OFF;
    float* tS = sm + TS_OFF;
    float* sp = sm + SP_OFF;
    float4* ex = (float4*)(sm + EX_OFF);    // [2][16][9]
    float* sx = sm + SX_OFF;

    const int b    = blockIdx.y;
    const int rank = blockIdx.x;
    const int t    = threadIdx.x;
    const int lane = t & 31;
    const int wp   = t >> 5;                 // 0..31

    // ---- load x slice [288][32] ----
    {
        const float4* src = (const float4*)&x[((size_t)b * NCAPS + rank * NPC) * ILEN];
        float4* dst = (float4*)xs;
        #pragma unroll
        for (int k = 0; k < 3; k++) {
            const int idx = t + k * TPB;
            if (idx < NPC * ILEN / 4) dst[idx] = src[idx];
        }
    }
    __syncthreads();

    // ---- iter 0: colsum partial -> broadcast to all peers ----
    {
        float acc = 0.f;
        #pragma unroll
        for (int k = 0; k < NPC / NWARP; k++)       // 9 rows per warp
            acc += xs[(wp + k * NWARP) * ILEN + lane];
        lp[wp * 32 + lane] = acc;
        __syncthreads();
        if (t < 32) {
            float s = 0.f;
            #pragma unroll
            for (int k = 0; k < NWARP; k++) s += lp[k * 32 + t];
            const unsigned int la = smem_u32(&sx[rank * 32 + t]);
            #pragma unroll
            for (int p = 0; p < CLU; p++) st_clu(mapa_rank(la, p), s);
        }
    }
    CLUSTER_SYNC();

    float t_acc = 0.f;   // cumulative t[o][i=lane], valid in warps wp<16

    // ================= 3 iterations =================
    for (int iter = 0; iter < 3; iter++) {
        if (iter > 0) {
            // ---- phase 1: warp pair (half, pair); lane owns o1 ----
            const int half = wp >> 4;          // 0: o=lane, 1: o=lane+32
            const int pair = wp & 15;          // n range [pair*18, pair*18+18)
            const int o1   = lane + 32 * half;

            unsigned long long tp[16];
            {
                const ulonglong2* a = (const ulonglong2*)&tS[o1 * 36];
                #pragma unroll
                for (int m = 0; m < 8; m++) {
                    const ulonglong2 v = a[m];
                    tp[2*m] = v.x; tp[2*m+1] = v.y;
                }
            }

            #pragma unroll
            for (int chunk = 0; chunk < 2; chunk++) {
                float e_arr[9];
                #pragma unroll
                for (int k = 0; k < 9; k++) {
                    const int n = pair * 18 + chunk * 9 + k;
                    unsigned long long acc = 0;
                    const ulonglong2* xr = (const ulonglong2*)&xs[n * ILEN];
                    #pragma unroll
                    for (int m = 0; m < 8; m++) {
                        const ulonglong2 v = xr[m];
                        ffma2(acc, tp[2*m], v.x);
                        ffma2(acc, tp[2*m+1], v.y);
                    }
                    const float2 u = unpack2(acc);
                    const float d = u.x + u.y;
                    float mx = d;
                    #pragma unroll
                    for (int off = 16; off; off >>= 1)
                        mx = fmaxf(mx, __shfl_xor_sync(0xffffffffu, mx, off));
                    const float e = __expf(d - mx);
                    e_arr[k] = e;
                    float sme = e;
                    #pragma unroll
                    for (int off = 16; off; off >>= 1)
                        sme += __shfl_xor_sync(0xffffffffu, sme, off);
                    if (lane == 0) {
                        float2* dst = (float2*)&ex[(chunk * 16 + pair) * 9 + k];
                        dst[half] = make_float2(mx, sme);
                    }
                }
                __syncthreads();
                #pragma unroll
                for (int k = 0; k < 9; k++) {
                    const int n = pair * 18 + chunk * 9 + k;
                    const float4 v = ex[(chunk * 16 + pair) * 9 + k];
                    const float M = fmaxf(v.x, v.z);
                    const float S = __expf(v.x - M) * v.y + __expf(v.z - M) * v.w;
                    const float myMx = half ? v.z : v.x;
                    ps[n * OCAPS + o1] = e_arr[k] * __expf(myMx - M) * (1.0f / S);
                }
            }
            __syncthreads();

            // ---- phase 2: 4 n-groups x 8 warps x 8 o (o-packed FFMA2) ----
            const int g  = wp >> 3;            // n group: [g*72, g*72+72)
            const int ow = (wp & 7) * 8;       // 8 o's
            unsigned long long ac0 = 0, ac1 = 0, ac2 = 0, ac3 = 0;
            const int nbeg = g * (NPC / 4);
            #pragma unroll 4
            for (int n = nbeg; n < nbeg + NPC / 4; n++) {
                const unsigned long long xx = splat2(xs[n * ILEN + lane]);
                const ulonglong2* pp = (const ulonglong2*)&ps[n * OCAPS + ow];
                const ulonglong2 p0 = pp[0];
                const ulonglong2 p1 = pp[1];
                ffma2(ac0, p0.x, xx); ffma2(ac1, p0.y, xx);
                ffma2(ac2, p1.x, xx); ffma2(ac3, p1.y, xx);
            }
            {
                const float2 u0 = unpack2(ac0), u1 = unpack2(ac1);
                const float2 u2 = unpack2(ac2), u3 = unpack2(ac3);
                float* dst = &lp[(g * OCAPS + ow) * 32 + lane];
                dst[0]   = u0.x; dst[32]  = u0.y;
                dst[64]  = u1.x; dst[96]  = u1.y;
                dst[128] = u2.x; dst[160] = u2.y;
                dst[192] = u3.x; dst[224] = u3.y;
            }
            __syncthreads();

            // ---- combine 4 groups, send to owner CTA ----
            #pragma unroll
            for (int h = 0; h < 2; h++) {
                const int oo = wp + h * 32;
                const float val = lp[(0 * OCAPS + oo) * 32 + lane]
                                + lp[(1 * OCAPS + oo) * 32 + lane]
                                + lp[(2 * OCAPS + oo) * 32 + lane]
                                + lp[(3 * OCAPS + oo) * 32 + lane];
                const unsigned int owner = (unsigned int)(oo >> 4);
                const int ol = oo & 15;
                const unsigned int la = smem_u32(&sp[(rank * OPC + ol) * 32 + lane]);
                st_clu(mapa_rank(la, owner), val);
            }
            CLUSTER_SYNC();
        }

        // ---- out/t step: warps 0..15 own one o each ----
        if (wp < OPC) {
            const int o = rank * OPC + wp;
            float s_l;
            if (iter == 0) {
                s_l = (sx[lane] + sx[32 + lane] + sx[64 + lane] + sx[96 + lane])
                      * (1.0f / OCAPS);
            } else {
                s_l = sp[(0 * OPC + wp) * 32 + lane] + sp[(1 * OPC + wp) * 32 + lane]
                    + sp[(2 * OPC + wp) * 32 + lane] + sp[(3 * OPC + wp) * 32 + lane];
            }

            float wrow[32];
            {
                const float4* wpp = (const float4*)&w[((size_t)o * OLEN + lane) * ILEN];
                #pragma unroll
                for (int m = 0; m < 8; m++) {
                    const float4 v = wpp[m];
                    wrow[m*4+0]=v.x; wrow[m*4+1]=v.y; wrow[m*4+2]=v.z; wrow[m*4+3]=v.w;
                }
            }
            float out_l = 0.f;
            #pragma unroll
            for (int i = 0; i < 32; i++)
                out_l += wrow[i] * __shfl_sync(0xffffffffu, s_l, i);

            float ss = out_l * out_l;
            #pragma unroll
            for (int off = 16; off; off >>= 1)
                ss += __shfl_xor_sync(0xffffffffu, ss, off);
            out_l *= sqrtf(ss) / (1.0f + ss);

            if (iter == 2) {
                out[((size_t)b * OCAPS + o) * OLEN + lane] = out_l;
            } else {
                float t_l = 0.f;
                #pragma unroll
                for (int l = 0; l < 32; l++)
                    t_l += w[((size_t)o * OLEN + l) * ILEN + lane] *
                           __shfl_sync(0xffffffffu, out_l, l);
                t_acc += t_l;
                const unsigned int la = smem_u32(&tS[o * 36 + lane]);
                #pragma unroll
                for (int p = 0; p < CLU; p++) st_clu(mapa_rank(la, p), t_acc);
            }
        }
        if (iter < 2) CLUSTER_SYNC();
    }
}

// ---------------------------------------------------------------------------
extern "C" void kernel_launch(void* const* d_in, const int* in_sizes, int n_in,
                              void* d_out, int out_size) {
    const float* x = (const float*)d_in[0];   // [32,1152,32]
    const float* w = (const float*)d_in[1];   // [64,32,32]
    float* out = (float*)d_out;               // [32,64,32]

    cudaFuncSetAttribute(k_caps, cudaFuncAttributeMaxDynamicSharedMemorySize,
                         SM_BYTES);
    k_caps<<<dim3(CLU, BATCH), TPB, SM_BYTES>>>(x, w, out);
}

// round 12
// speedup vs baseline: 1.4216x; 1.4216x over previous
#include <cuda_runtime.h>
#include <cuda_bf16.h>
#include <cstdint>
#include <stdint.h>
#include <math.h>

#define BATCH   32
#define NCAPS   1152
#define ILEN    32
#define OCAPS   64
#define OLEN    32
#define CLU     4                  // CTAs per cluster (one cluster per batch)
#define NPC     (NCAPS / CLU)      // 288 input caps per CTA
#define OPC     (OCAPS / CLU)      // 16 output caps per CTA
#define TPB     512
#define NWARP   16
#define NPW     (NPC / NWARP)      // 18 n per warp in phase 1

// SMEM layout (float offsets)
#define XS_OFF  0                          // [288][32]         9216
#define PS_OFF  (XS_OFF + NPC * ILEN)      // [288][64]        18432
#define TS_OFF  (PS_OFF + NPC * OCAPS)     // [64][36] padded   2304
#define SP_OFF  (TS_OFF + OCAPS * 36)      // [8][16][32]       4096
#define SX_OFF  (SP_OFF + 8 * OPC * 32)    // [4][32]            128
#define SM_FLOATS (SX_OFF + CLU * 32)
#define SM_BYTES  (SM_FLOATS * 4)          // 136,704 B

__device__ __forceinline__ unsigned int smem_u32(const void* p) {
    unsigned int a;
    asm("{ .reg .u64 t; cvta.to.shared.u64 t, %1; cvt.u32.u64 %0, t; }"
        : "=r"(a) : "l"(p));
    return a;
}
__device__ __forceinline__ unsigned int mapa_rank(unsigned int laddr,
                                                  unsigned int rank) {
    unsigned int r;
    asm("mapa.shared::cluster.u32 %0, %1, %2;" : "=r"(r) : "r"(laddr), "r"(rank));
    return r;
}
__device__ __forceinline__ void st_clu(unsigned int raddr, float v) {
    asm volatile("st.shared::cluster.f32 [%0], %1;" :: "r"(raddr), "f"(v) : "memory");
}
#define CLUSTER_SYNC() do { \
    asm volatile("barrier.cluster.arrive.aligned;" ::: "memory"); \
    asm volatile("barrier.cluster.wait.aligned;" ::: "memory"); \
} while (0)

// packed fp32x2 helpers (FFMA2 path — only reachable via PTX)
__device__ __forceinline__ void ffma2(unsigned long long& d,
                                      unsigned long long a,
                                      unsigned long long b) {
    asm("fma.rn.f32x2 %0, %1, %2, %0;" : "+l"(d) : "l"(a), "l"(b));
}
__device__ __forceinline__ float2 unpack2(unsigned long long v) {
    float2 r;
    asm("mov.b64 {%0, %1}, %2;" : "=f"(r.x), "=f"(r.y) : "l"(v));
    return r;
}
__device__ __forceinline__ unsigned long long splat2(float v) {
    unsigned long long r;
    asm("mov.b64 %0, {%1, %1};" : "=l"(r) : "f"(v));
    return r;
}

// ---------------------------------------------------------------------------
// One persistent clustered kernel: all 3 routing iterations for one batch
// per 4-CTA cluster. x-slice, probs, t, partial-s all SMEM/DSMEM resident.
// ---------------------------------------------------------------------------
__global__ void __cluster_dims__(CLU, 1, 1) __launch_bounds__(TPB, 1)
k_caps(const float* __restrict__ x, const float* __restrict__ w,
       float* __restrict__ out) {
    extern __shared__ float sm[];
    float* xs = sm + XS_OFF;
    float* ps = sm + PS_OFF;
    float* tS = sm + TS_OFF;
    float* sp = sm + SP_OFF;
    float* sx = sm + SX_OFF;

    const int b    = blockIdx.y;
    const int rank = blockIdx.x;
    const int t    = threadIdx.x;
    const int lane = t & 31;
    const int wp   = t >> 5;
    const int o    = rank * OPC + wp;      // this warp's owned output capsule

    // ---- load x slice [288][32] ----
    {
        const float4* src = (const float4*)&x[((size_t)b * NCAPS + rank * NPC) * ILEN];
        float4* dst = (float4*)xs;
        #pragma unroll
        for (int idx = t; idx < NPC * ILEN / 4; idx += TPB) dst[idx] = src[idx];
    }
    __syncthreads();

    // ---- iter 0: colsum partial -> broadcast to all peers ----
    {
        float acc = 0.f;
        #pragma unroll
        for (int k = 0; k < NPW; k++)
            acc += xs[(wp + k * NWARP) * ILEN + lane];
        float* red = ps;                   // reuse ps area
        red[wp * 32 + lane] = acc;
        __syncthreads();
        if (t < 32) {
            float s = 0.f;
            #pragma unroll
            for (int k = 0; k < NWARP; k++) s += red[k * 32 + t];
            const unsigned int la = smem_u32(&sx[rank * 32 + t]);
            #pragma unroll
            for (int p = 0; p < CLU; p++) st_clu(mapa_rank(la, p), s);
        }
    }
    CLUSTER_SYNC();

    float t_acc = 0.f;   // cumulative t[o][i=lane] across iterations

    // ================= 3 iterations =================
    for (int iter = 0; iter < 3; iter++) {
        if (iter > 0) {
            // ---- phase 1: logits + softmax, 3-way n ILP (18 = 6x3) ----
            unsigned long long tp0[16], tp1[16];
            {
                const ulonglong2* a = (const ulonglong2*)&tS[lane * 36];
                const ulonglong2* c = (const ulonglong2*)&tS[(lane + 32) * 36];
                #pragma unroll
                for (int m = 0; m < 8; m++) {
                    ulonglong2 v = a[m];
                    tp0[2*m] = v.x; tp0[2*m+1] = v.y;
                    v = c[m];
                    tp1[2*m] = v.x; tp1[2*m+1] = v.y;
                }
            }
            #pragma unroll
            for (int k = 0; k < NPW; k += 3) {
                const int na = wp * NPW + k;
                unsigned long long acc[3][2] = {{0,0},{0,0},{0,0}};
                #pragma unroll
                for (int j = 0; j < 3; j++) {
                    const ulonglong2* xr = (const ulonglong2*)&xs[(na + j) * ILEN];
                    #pragma unroll
                    for (int m = 0; m < 8; m++) {
                        const ulonglong2 v = xr[m];
                        ffma2(acc[j][0], tp0[2*m], v.x);
                        ffma2(acc[j][0], tp0[2*m+1], v.y);
                        ffma2(acc[j][1], tp1[2*m], v.x);
                        ffma2(acc[j][1], tp1[2*m+1], v.y);
                    }
                }
                float d0[3], d1[3], mx[3];
                #pragma unroll
                for (int j = 0; j < 3; j++) {
                    const float2 u0 = unpack2(acc[j][0]);
                    const float2 u1 = unpack2(acc[j][1]);
                    d0[j] = u0.x + u0.y;
                    d1[j] = u1.x + u1.y;
                    mx[j] = fmaxf(d0[j], d1[j]);
                }
                #pragma unroll
                for (int off = 16; off; off >>= 1) {
                    #pragma unroll
                    for (int j = 0; j < 3; j++)
                        mx[j] = fmaxf(mx[j], __shfl_xor_sync(0xffffffffu, mx[j], off));
                }
                float e0[3], e1[3], s[3];
                #pragma unroll
                for (int j = 0; j < 3; j++) {
                    e0[j] = __expf(d0[j] - mx[j]);
                    e1[j] = __expf(d1[j] - mx[j]);
                    s[j] = e0[j] + e1[j];
                }
                #pragma unroll
                for (int off = 16; off; off >>= 1) {
                    #pragma unroll
                    for (int j = 0; j < 3; j++)
                        s[j] += __shfl_xor_sync(0xffffffffu, s[j], off);
                }
                #pragma unroll
                for (int j = 0; j < 3; j++) {
                    const float inv = __fdividef(1.0f, s[j]);
                    ps[(na + j) * OCAPS + lane]      = e0[j] * inv;
                    ps[(na + j) * OCAPS + lane + 32] = e1[j] * inv;
                }
            }
            __syncthreads();

            // ---- phase 2: o-packed partial s; 2 n-groups x 8 warps x 8 o ----
            const int group = wp >> 3;
            const int ow    = (wp & 7) * 8;
            unsigned long long ac0 = 0, ac1 = 0, ac2 = 0, ac3 = 0;
            const int nbeg = group * (NPC / 2);
            #pragma unroll 4
            for (int n = nbeg; n < nbeg + NPC / 2; n++) {
                const unsigned long long xx = splat2(xs[n * ILEN + lane]);
                const ulonglong2* pp = (const ulonglong2*)&ps[n * OCAPS + ow];
                const ulonglong2 p0 = pp[0];
                const ulonglong2 p1 = pp[1];
                ffma2(ac0, p0.x, xx); ffma2(ac1, p0.y, xx);
                ffma2(ac2, p1.x, xx); ffma2(ac3, p1.y, xx);
            }
            // deliver 8 o-rows to owner CTA's slot [rank*2+group]
            {
                const unsigned int owner = (unsigned int)(ow >> 4);
                const int ol   = ow & 15;            // 0 or 8
                const int slot = rank * 2 + group;
                const unsigned int la =
                    smem_u32(&sp[(slot * OPC + ol) * 32 + lane]);
                const unsigned int ra = mapa_rank(la, owner);
                const float2 u0 = unpack2(ac0), u1 = unpack2(ac1);
                const float2 u2 = unpack2(ac2), u3 = unpack2(ac3);
                st_clu(ra +   0, u0.x); st_clu(ra + 128, u0.y);
                st_clu(ra + 256, u1.x); st_clu(ra + 384, u1.y);
                st_clu(ra + 512, u2.x); st_clu(ra + 640, u2.y);
                st_clu(ra + 768, u3.x); st_clu(ra + 896, u3.y);
            }
            CLUSTER_SYNC();
        }

        // ---- out/t step: warp handles its owned o ----
        float s_l;
        if (iter == 0) {
            s_l = (sx[lane] + sx[32 + lane] + sx[64 + lane] + sx[96 + lane])
                  * (1.0f / OCAPS);
        } else {
            s_l = 0.f;
            #pragma unroll
            for (int slot = 0; slot < 8; slot++)
                s_l += sp[(slot * OPC + wp) * 32 + lane];
        }

        float wrow[32];
        {
            const float4* wpp = (const float4*)&w[((size_t)o * OLEN + lane) * ILEN];
            #pragma unroll
            for (int m = 0; m < 8; m++) {
                const float4 v = wpp[m];
                wrow[m*4+0]=v.x; wrow[m*4+1]=v.y; wrow[m*4+2]=v.z; wrow[m*4+3]=v.w;
            }
        }
        float out_l = 0.f;
        #pragma unroll
        for (int i = 0; i < 32; i++)
            out_l += wrow[i] * __shfl_sync(0xffffffffu, s_l, i);

        float ss = out_l * out_l;
        #pragma unroll
        for (int off = 16; off; off >>= 1)
            ss += __shfl_xor_sync(0xffffffffu, ss, off);
        out_l *= __fdividef(sqrtf(ss), 1.0f + ss);

        if (iter == 2) {
            out[((size_t)b * OCAPS + o) * OLEN + lane] = out_l;
        } else {
            // t[o][i=lane] this iteration; accumulate cumulatively in register
            float t_l = 0.f;
            #pragma unroll
            for (int l = 0; l < 32; l++)
                t_l += w[((size_t)o * OLEN + l) * ILEN + lane] *
                       __shfl_sync(0xffffffffu, out_l, l);
            t_acc += t_l;
            const unsigned int la = smem_u32(&tS[o * 36 + lane]);
            #pragma unroll
            for (int p = 0; p < CLU; p++) st_clu(mapa_rank(la, p), t_acc);
            CLUSTER_SYNC();
        }
    }
}

// ---------------------------------------------------------------------------
extern "C" void kernel_launch(void* const* d_in, const int* in_sizes, int n_in,
                              void* d_out, int out_size) {
    const float* x = (const float*)d_in[0];   // [32,1152,32]
    const float* w = (const float*)d_in[1];   // [64,32,32]
    float* out = (float*)d_out;               // [32,64,32]

    cudaFuncSetAttribute(k_caps, cudaFuncAttributeMaxDynamicSharedMemorySize,
                         SM_BYTES);
    k_caps<<<dim3(CLU, BATCH), TPB, SM_BYTES>>>(x, w, out);
}

// round 13
// speedup vs baseline: 1.5009x; 1.0557x over previous
#include <cuda_runtime.h>
#include <cuda_bf16.h>
#include <cstdint>
#include <stdint.h>
#include <math.h>

#define BATCH   32
#define NCAPS   1152
#define ILEN    32
#define OCAPS   64
#define OLEN    32
#define CLU     4                  // CTAs per cluster (one cluster per batch)
#define NPC     (NCAPS / CLU)      // 288 input caps per CTA
#define OPC     (OCAPS / CLU)      // 16 output caps per CTA
#define TPB     512
#define NWARP   16
#define NPW     (NPC / NWARP)      // 18 n per warp in phase 1

// SMEM layout (float offsets)
#define XS_OFF  0                            // xs  [288][32]      9216
#define PS_OFF  (XS_OFF + NPC * ILEN)        // ps  [288][64]     18432
#define TT_OFF  (PS_OFF + NPC * OCAPS)       // tT2 [16][64] f2    2048
#define SP_OFF  (TT_OFF + 16 * OCAPS * 2)    // sp  [8][16][32]    4096
#define SX_OFF  (SP_OFF + 8 * OPC * 32)      // sx  [4][32]         128
#define WS_OFF  (SX_OFF + CLU * 32)          // Wsm [16][32][33]  16896
#define SM_FLOATS (WS_OFF + OPC * 32 * 33)
#define SM_BYTES  (SM_FLOATS * 4)            // 203,264 B

__device__ __forceinline__ unsigned int smem_u32(const void* p) {
    unsigned int a;
    asm("{ .reg .u64 t; cvta.to.shared.u64 t, %1; cvt.u32.u64 %0, t; }"
        : "=r"(a) : "l"(p));
    return a;
}
__device__ __forceinline__ unsigned int mapa_rank(unsigned int laddr,
                                                  unsigned int rank) {
    unsigned int r;
    asm("mapa.shared::cluster.u32 %0, %1, %2;" : "=r"(r) : "r"(laddr), "r"(rank));
    return r;
}
__device__ __forceinline__ void st_clu(unsigned int raddr, float v) {
    asm volatile("st.shared::cluster.f32 [%0], %1;" :: "r"(raddr), "f"(v) : "memory");
}
#define CLUSTER_SYNC() do { \
    asm volatile("barrier.cluster.arrive.aligned;" ::: "memory"); \
    asm volatile("barrier.cluster.wait.aligned;" ::: "memory"); \
} while (0)

// packed fp32x2 helpers (FFMA2 path — only reachable via PTX)
__device__ __forceinline__ void ffma2(unsigned long long& d,
                                      unsigned long long a,
                                      unsigned long long b) {
    asm("fma.rn.f32x2 %0, %1, %2, %0;" : "+l"(d) : "l"(a), "l"(b));
}
__device__ __forceinline__ float2 unpack2(unsigned long long v) {
    float2 r;
    asm("mov.b64 {%0, %1}, %2;" : "=f"(r.x), "=f"(r.y) : "l"(v));
    return r;
}
__device__ __forceinline__ unsigned long long splat2(float v) {
    unsigned long long r;
    asm("mov.b64 %0, {%1, %1};" : "=l"(r) : "f"(v));
    return r;
}

// ---------------------------------------------------------------------------
// One persistent clustered kernel: all 3 routing iterations for one batch
// per 4-CTA cluster. x, probs, t, partial-s, W all SMEM/DSMEM resident.
// ---------------------------------------------------------------------------
__global__ void __cluster_dims__(CLU, 1, 1) __launch_bounds__(TPB, 1)
k_caps(const float* __restrict__ x, const float* __restrict__ w,
       float* __restrict__ out) {
    extern __shared__ float sm[];
    float* xs  = sm + XS_OFF;
    float* ps  = sm + PS_OFF;
    float* tT  = sm + TT_OFF;    // [j=i/2][o] float2 (packed i-pairs)
    float* sp  = sm + SP_OFF;
    float* sx  = sm + SX_OFF;
    float* Wsm = sm + WS_OFF;    // [oo][l][33]

    const int b    = blockIdx.y;
    const int rank = blockIdx.x;
    const int t    = threadIdx.x;
    const int lane = t & 31;
    const int wp   = t >> 5;
    const int o    = rank * OPC + wp;      // this warp's owned output capsule

    // ---- load x slice [288][32] ----
    {
        const float4* src = (const float4*)&x[((size_t)b * NCAPS + rank * NPC) * ILEN];
        float4* dst = (float4*)xs;
        #pragma unroll
        for (int idx = t; idx < NPC * ILEN / 4; idx += TPB) dst[idx] = src[idx];
    }
    // ---- load W slice for this CTA's 16 o's into SMEM [oo][l][33] ----
    {
        const float* wsrc = &w[(size_t)(rank * OPC) * OLEN * ILEN];
        #pragma unroll
        for (int idx = t; idx < OPC * OLEN * ILEN; idx += TPB) {
            const int oo  = idx >> 10;
            const int rem = idx & 1023;
            Wsm[oo * (32 * 33) + (rem >> 5) * 33 + (rem & 31)] = wsrc[idx];
        }
    }
    __syncthreads();

    // ---- iter 0: colsum partial -> broadcast to all peers ----
    {
        float acc = 0.f;
        #pragma unroll
        for (int k = 0; k < NPW; k++)
            acc += xs[(wp + k * NWARP) * ILEN + lane];
        float* red = ps;                   // reuse ps area
        red[wp * 32 + lane] = acc;
        __syncthreads();
        if (t < 32) {
            float s = 0.f;
            #pragma unroll
            for (int k = 0; k < NWARP; k++) s += red[k * 32 + t];
            const unsigned int la = smem_u32(&sx[rank * 32 + t]);
            #pragma unroll
            for (int p = 0; p < CLU; p++) st_clu(mapa_rank(la, p), s);
        }
    }
    CLUSTER_SYNC();

    float t_acc = 0.f;   // cumulative t[o][i=lane] across iterations

    // ================= 3 iterations =================
    for (int iter = 0; iter < 3; iter++) {
        if (iter > 0) {
            // ---- phase 1: logits + softmax, 6-way n ILP (18 = 3x6) ----
            // t rows for o=lane, o=lane+32 from packed tT2 (conflict-free u64)
            unsigned long long tp0[16], tp1[16];
            #pragma unroll
            for (int j = 0; j < 16; j++) {
                tp0[j] = *(const unsigned long long*)&tT[(j * OCAPS + lane) * 2];
                tp1[j] = *(const unsigned long long*)&tT[(j * OCAPS + lane + 32) * 2];
            }
            #pragma unroll
            for (int k = 0; k < NPW; k += 6) {
                const int na = wp * NPW + k;
                unsigned long long acc[6][2];
                #pragma unroll
                for (int j = 0; j < 6; j++) { acc[j][0] = 0; acc[j][1] = 0; }
                #pragma unroll
                for (int j = 0; j < 6; j++) {
                    const ulonglong2* xr = (const ulonglong2*)&xs[(na + j) * ILEN];
                    #pragma unroll
                    for (int m = 0; m < 8; m++) {
                        const ulonglong2 v = xr[m];
                        ffma2(acc[j][0], tp0[2*m], v.x);
                        ffma2(acc[j][0], tp0[2*m+1], v.y);
                        ffma2(acc[j][1], tp1[2*m], v.x);
                        ffma2(acc[j][1], tp1[2*m+1], v.y);
                    }
                }
                float d0[6], d1[6], mx[6];
                #pragma unroll
                for (int j = 0; j < 6; j++) {
                    const float2 u0 = unpack2(acc[j][0]);
                    const float2 u1 = unpack2(acc[j][1]);
                    d0[j] = u0.x + u0.y;
                    d1[j] = u1.x + u1.y;
                    mx[j] = fmaxf(d0[j], d1[j]);
                }
                #pragma unroll
                for (int off = 16; off; off >>= 1) {
                    #pragma unroll
                    for (int j = 0; j < 6; j++)
                        mx[j] = fmaxf(mx[j], __shfl_xor_sync(0xffffffffu, mx[j], off));
                }
                float e0[6], e1[6], s[6];
                #pragma unroll
                for (int j = 0; j < 6; j++) {
                    e0[j] = __expf(d0[j] - mx[j]);
                    e1[j] = __expf(d1[j] - mx[j]);
                    s[j] = e0[j] + e1[j];
                }
                #pragma unroll
                for (int off = 16; off; off >>= 1) {
                    #pragma unroll
                    for (int j = 0; j < 6; j++)
                        s[j] += __shfl_xor_sync(0xffffffffu, s[j], off);
                }
                #pragma unroll
                for (int j = 0; j < 6; j++) {
                    const float inv = __fdividef(1.0f, s[j]);
                    ps[(na + j) * OCAPS + lane]      = e0[j] * inv;
                    ps[(na + j) * OCAPS + lane + 32] = e1[j] * inv;
                }
            }
            __syncthreads();

            // ---- phase 2: o-packed partial s; 2 n-groups x 8 warps x 8 o ----
            const int group = wp >> 3;
            const int ow    = (wp & 7) * 8;
            unsigned long long ac0 = 0, ac1 = 0, ac2 = 0, ac3 = 0;
            const int nbeg = group * (NPC / 2);
            #pragma unroll 8
            for (int n = nbeg; n < nbeg + NPC / 2; n++) {
                const unsigned long long xx = splat2(xs[n * ILEN + lane]);
                const ulonglong2* pp = (const ulonglong2*)&ps[n * OCAPS + ow];
                const ulonglong2 p0 = pp[0];
                const ulonglong2 p1 = pp[1];
                ffma2(ac0, p0.x, xx); ffma2(ac1, p0.y, xx);
                ffma2(ac2, p1.x, xx); ffma2(ac3, p1.y, xx);
            }
            // deliver 8 o-rows to owner CTA's slot [rank*2+group]
            {
                const unsigned int owner = (unsigned int)(ow >> 4);
                const int ol   = ow & 15;            // 0 or 8
                const int slot = rank * 2 + group;
                const unsigned int la =
                    smem_u32(&sp[(slot * OPC + ol) * 32 + lane]);
                const unsigned int ra = mapa_rank(la, owner);
                const float2 u0 = unpack2(ac0), u1 = unpack2(ac1);
                const float2 u2 = unpack2(ac2), u3 = unpack2(ac3);
                st_clu(ra +   0, u0.x); st_clu(ra + 128, u0.y);
                st_clu(ra + 256, u1.x); st_clu(ra + 384, u1.y);
                st_clu(ra + 512, u2.x); st_clu(ra + 640, u2.y);
                st_clu(ra + 768, u3.x); st_clu(ra + 896, u3.y);
            }
            CLUSTER_SYNC();
        }

        // ---- out/t step: warp handles its owned o (W from SMEM) ----
        float s_l;
        if (iter == 0) {
            s_l = (sx[lane] + sx[32 + lane] + sx[64 + lane] + sx[96 + lane])
                  * (1.0f / OCAPS);
        } else {
            s_l = 0.f;
            #pragma unroll
            for (int slot = 0; slot < 8; slot++)
                s_l += sp[(slot * OPC + wp) * 32 + lane];
        }

        const float* wtile = &Wsm[wp * (32 * 33)];
        float out_l = 0.f;
        #pragma unroll
        for (int i = 0; i < 32; i++)
            out_l += wtile[lane * 33 + i] * __shfl_sync(0xffffffffu, s_l, i);

        float ss = out_l * out_l;
        #pragma unroll
        for (int off = 16; off; off >>= 1)
            ss += __shfl_xor_sync(0xffffffffu, ss, off);
        out_l *= __fdividef(sqrtf(ss), 1.0f + ss);

        if (iter == 2) {
            out[((size_t)b * OCAPS + o) * OLEN + lane] = out_l;
        } else {
            // t[o][i=lane] this iteration; accumulate cumulatively in register
            float t_l = 0.f;
            #pragma unroll
            for (int l = 0; l < 32; l++)
                t_l += wtile[l * 33 + lane] * __shfl_sync(0xffffffffu, out_l, l);
            t_acc += t_l;
            // write packed-transposed: tT2[j = lane/2][o], element lane&1
            const unsigned int la =
                smem_u32(&tT[((lane >> 1) * OCAPS + o) * 2 + (lane & 1)]);
            #pragma unroll
            for (int p = 0; p < CLU; p++) st_clu(mapa_rank(la, p), t_acc);
            CLUSTER_SYNC();
        }
    }
}

// ---------------------------------------------------------------------------
extern "C" void kernel_launch(void* const* d_in, const int* in_sizes, int n_in,
                              void* d_out, int out_size) {
    const float* x = (const float*)d_in[0];   // [32,1152,32]
    const float* w = (const float*)d_in[1];   // [64,32,32]
    float* out = (float*)d_out;               // [32,64,32]

    cudaFuncSetAttribute(k_caps, cudaFuncAttributeMaxDynamicSharedMemorySize,
                         SM_BYTES);
    k_caps<<<dim3(CLU, BATCH), TPB, SM_BYTES>>>(x, w, out);
}